// round 4
// baseline (speedup 1.0000x reference)
#include <cuda_runtime.h>
#include <cstdint>

#define EPS 1e-5f
#define NUM_GRAPHS 128
#define MAX_N 131072
#define CLUSTER 8
#define CHUNK 12544              // 8 * 12544 = 100352 >= N=100000
#define CTA_THREADS 1024
#define NUM_CLUSTERS 18          // 144 CTAs ~= 1 per SM

// Exact per-node graph id (uint8; NUM_GRAPHS=128).
__device__ unsigned char g_batch8[MAX_N];

__global__ void prep_kernel(const int* __restrict__ batch_index,
                            float* __restrict__ out, int N) {
    int i = blockIdx.x * blockDim.x + threadIdx.x;
    if (i < NUM_GRAPHS) out[i] = 0.0f;
    if (i < N) g_batch8[i] = (unsigned char)batch_index[i];
}

__device__ __forceinline__ bool xing_test(float2 p1, float2 p2, float2 p3, float2 p4) {
    float rx = p4.x - p3.x, ry = p4.y - p3.y;
    float d1 = rx * (p1.y - p3.y) - ry * (p1.x - p3.x);
    float d2 = rx * (p2.y - p3.y) - ry * (p2.x - p3.x);
    float qx = p2.x - p1.x, qy = p2.y - p1.y;
    float d3 = qx * (p3.y - p1.y) - qy * (p3.x - p1.x);
    float d4 = qx * (p4.y - p1.y) - qy * (p4.x - p1.x);
    return (d1 * d2 < -EPS) & (d3 * d4 < -EPS);
}

// Gather node position from the cluster-distributed smem table.
__device__ __forceinline__ float2 dsmem_gather(uint32_t smem_base, unsigned n) {
    unsigned r = n / (unsigned)CHUNK;            // reciprocal-mul, ALU pipe (idle)
    unsigned off = n - r * (unsigned)CHUNK;
    uint32_t laddr = smem_base + off * 8u;
    uint32_t raddr;
    asm("mapa.shared::cluster.u32 %0, %1, %2;" : "=r"(raddr) : "r"(laddr), "r"(r));
    float2 v;
    asm volatile("ld.shared::cluster.v2.f32 {%0, %1}, [%2];"
                 : "=f"(v.x), "=f"(v.y) : "r"(raddr));
    return v;
}

__global__ void __launch_bounds__(CTA_THREADS, 1) __cluster_dims__(CLUSTER, 1, 1)
crossings_kernel(const float2* __restrict__ pos,
                 const int* __restrict__ epi,  // [2][2][P]: s1 | s2 | e1 | e2
                 float* __restrict__ out,
                 int P, int N) {
    extern __shared__ float2 s_pos[];           // CHUNK float2 = 100352 B
    __shared__ float hist[NUM_GRAPHS];

    uint32_t rank;
    asm("mov.u32 %0, %%cluster_ctarank;" : "=r"(rank));

    // Fill this CTA's chunk of node_pos (coalesced).
    int base = rank * CHUNK;
    for (int i = threadIdx.x; i < CHUNK; i += CTA_THREADS) {
        int n = base + i;
        s_pos[i] = (n < N) ? __ldg(pos + n) : make_float2(0.0f, 0.0f);
    }
    if (threadIdx.x < NUM_GRAPHS) hist[threadIdx.x] = 0.0f;
    __syncthreads();

    uint32_t smem_base;
    asm("{ .reg .u64 t; cvta.to.shared.u64 t, %1; cvt.u32.u64 %0, t; }"
        : "=r"(smem_base) : "l"(s_pos));

    // All cluster CTAs' tables must be resident before any remote gather.
    asm volatile("barrier.cluster.arrive.aligned;" ::: "memory");
    asm volatile("barrier.cluster.wait.aligned;" ::: "memory");

    const int P4 = P >> 2;
    const int4* __restrict__ s1v = (const int4*)(epi);
    const int4* __restrict__ s2v = (const int4*)(epi + (size_t)P);
    const int4* __restrict__ e1v = (const int4*)(epi + 2 * (size_t)P);
    const int4* __restrict__ e2v = (const int4*)(epi + 3 * (size_t)P);

    const int stride = gridDim.x * blockDim.x;

    for (int v = blockIdx.x * blockDim.x + threadIdx.x; v < P4; v += stride) {
        int4 s1 = __ldg(s1v + v);
        int4 s2 = __ldg(s2v + v);
        int4 e1 = __ldg(e1v + v);
        int4 e2 = __ldg(e2v + v);

        // 16 DSMEM gathers in flight (smem crossbar path, not L1tex).
        float2 a1 = dsmem_gather(smem_base, s1.x);
        float2 a2 = dsmem_gather(smem_base, e1.x);
        float2 a3 = dsmem_gather(smem_base, s2.x);
        float2 a4 = dsmem_gather(smem_base, e2.x);
        float2 b1 = dsmem_gather(smem_base, s1.y);
        float2 b2 = dsmem_gather(smem_base, e1.y);
        float2 b3 = dsmem_gather(smem_base, s2.y);
        float2 b4 = dsmem_gather(smem_base, e2.y);
        float2 c1 = dsmem_gather(smem_base, s1.z);
        float2 c2 = dsmem_gather(smem_base, e1.z);
        float2 c3 = dsmem_gather(smem_base, s2.z);
        float2 c4 = dsmem_gather(smem_base, e2.z);
        float2 d1 = dsmem_gather(smem_base, s1.w);
        float2 d2 = dsmem_gather(smem_base, e1.w);
        float2 d3 = dsmem_gather(smem_base, s2.w);
        float2 d4 = dsmem_gather(smem_base, e2.w);

        bool xa = xing_test(a1, a2, a3, a4);
        bool xb = xing_test(b1, b2, b3, b4);
        bool xc = xing_test(c1, c2, c3, c4);
        bool xd = xing_test(d1, d2, d3, d4);

        // Predicated batch gathers ride the now-idle L1tex path.
        if (xa) atomicAdd(&hist[g_batch8[s1.x]], 1.0f);
        if (xb) atomicAdd(&hist[g_batch8[s1.y]], 1.0f);
        if (xc) atomicAdd(&hist[g_batch8[s1.z]], 1.0f);
        if (xd) atomicAdd(&hist[g_batch8[s1.w]], 1.0f);
    }

    // Scalar tail (P not divisible by 4) — global loads, block 0 only.
    if (blockIdx.x == 0) {
        for (int p = (P4 << 2) + threadIdx.x; p < P; p += blockDim.x) {
            int t1 = __ldg(epi + p);
            int t2 = __ldg(epi + (size_t)P + p);
            int t3 = __ldg(epi + 2 * (size_t)P + p);
            int t4 = __ldg(epi + 3 * (size_t)P + p);
            if (xing_test(__ldg(pos + t1), __ldg(pos + t3),
                          __ldg(pos + t2), __ldg(pos + t4)))
                atomicAdd(&hist[g_batch8[t1]], 1.0f);
        }
    }

    __syncthreads();
    for (int i = threadIdx.x; i < NUM_GRAPHS; i += CTA_THREADS) {
        float h = hist[i];
        if (h != 0.0f) atomicAdd(&out[i], h);
    }

    // Keep smem alive until every cluster peer finished its remote reads.
    asm volatile("barrier.cluster.arrive.aligned;" ::: "memory");
    asm volatile("barrier.cluster.wait.aligned;" ::: "memory");
}

extern "C" void kernel_launch(void* const* d_in, const int* in_sizes, int n_in,
                              void* d_out, int out_size) {
    // metadata order: node_pos f32[N,2], edge_index i32[2,E] (UNUSED),
    //                 apsp f32[E] (UNUSED), batch_index i32[N],
    //                 edge_pair_index i32[2,2,P]
    const float2* pos = (const float2*)d_in[0];
    const int* batch_index = (const int*)d_in[3];
    const int* epi = (const int*)d_in[4];
    float* out = (float*)d_out;

    int N = in_sizes[0] / 2;
    if (N > MAX_N) N = MAX_N;        // scratch bound (N is 100000 by spec)
    int P = in_sizes[4] / 4;

    int prep_threads = 256;
    int prep_blocks = (N + prep_threads - 1) / prep_threads;
    prep_kernel<<<prep_blocks, prep_threads>>>(batch_index, out, N);

    size_t smem_bytes = (size_t)CHUNK * sizeof(float2);   // 100352 B
    static bool attr_set = false;
    if (!attr_set) {
        cudaFuncSetAttribute(crossings_kernel,
                             cudaFuncAttributeMaxDynamicSharedMemorySize,
                             (int)smem_bytes);
        attr_set = true;
    }

    crossings_kernel<<<NUM_CLUSTERS * CLUSTER, CTA_THREADS, smem_bytes>>>(
        pos, epi, out, P, N);
}

// round 5
// speedup vs baseline: 4.5897x; 4.5897x over previous
#include <cuda_runtime.h>
#include <cstdint>

#define EPS 1e-5f
#define NUM_GRAPHS 128
#define MAX_N 131072
#define F_SMEM 55296              // nodes held quantized in smem (221184 B)
#define NG16_MAX 8192             // 16-node coarse groups
#define QSCALE 2.44140625e-4f     // 8/32768
#define QINV 4096.0f              // 32768/8
#define CTA_THREADS 1024

// Exact per-node graph id (uint8; NUM_GRAPHS=128 < 255 sentinel).
__device__ unsigned char g_batch8[MAX_N];
// Batch of 16-node group if uniform, else 255.
__device__ unsigned char g_coarse16[NG16_MAX];

__global__ void prep_kernel(const int* __restrict__ batch_index,
                            float* __restrict__ out, int N) {
    int i = blockIdx.x * blockDim.x + threadIdx.x;
    if (i < NUM_GRAPHS) out[i] = 0.0f;
    if (i < N) g_batch8[i] = (unsigned char)batch_index[i];
}

__global__ void prep_coarse_kernel(int N) {
    int g = blockIdx.x * blockDim.x + threadIdx.x;
    int ng = (N + 15) >> 4;
    if (g >= ng) return;
    int base = g << 4;
    unsigned char b0 = g_batch8[base];
    unsigned char v = b0;
    int lim = min(16, N - base);
    for (int j = 1; j < lim; j++)
        if (g_batch8[base + j] != b0) { v = 255; break; }
    g_coarse16[g] = v;
}

__device__ __forceinline__ bool xing_test(float2 p1, float2 p2, float2 p3, float2 p4) {
    float rx = p4.x - p3.x, ry = p4.y - p3.y;
    float d1 = rx * (p1.y - p3.y) - ry * (p1.x - p3.x);
    float d2 = rx * (p2.y - p3.y) - ry * (p2.x - p3.x);
    float qx = p2.x - p1.x, qy = p2.y - p1.y;
    float d3 = qx * (p3.y - p1.y) - qy * (p3.x - p1.x);
    float d4 = qx * (p4.y - p1.y) - qy * (p4.x - p1.x);
    return (d1 * d2 < -EPS) & (d3 * d4 < -EPS);
}

// Mixed-path position fetch: smem (quantized, crossbar) or L1tex (exact).
__device__ __forceinline__ float2 get_pos(const float2* __restrict__ pos,
                                          const uint32_t* __restrict__ s_qpos,
                                          int idx, int F) {
    if (idx < F) {
        uint32_t q = s_qpos[idx];
        short sx = (short)(q & 0xFFFFu);
        short sy = (short)(q >> 16);
        return make_float2((float)sx * QSCALE, (float)sy * QSCALE);
    }
    return __ldg(pos + idx);
}

__global__ void __launch_bounds__(CTA_THREADS, 1)
crossings_kernel(const float2* __restrict__ pos,
                 const int* __restrict__ epi,  // [2][2][P]: s1 | s2 | e1 | e2
                 float* __restrict__ out,
                 int P, int N, int F, int NG16) {
    extern __shared__ char smem_raw[];
    uint32_t* s_qpos = (uint32_t*)smem_raw;                 // F * 4 bytes
    unsigned char* s_coarse = (unsigned char*)(smem_raw + (size_t)F * 4);
    float* hist = (float*)(smem_raw + (size_t)F * 4 + ((NG16 + 15) & ~15));

    // Preload: quantize first F node positions into smem (coalesced reads).
    for (int i = threadIdx.x; i < F; i += CTA_THREADS) {
        float2 p = __ldg(pos + i);
        int qx = __float2int_rn(p.x * QINV);
        int qy = __float2int_rn(p.y * QINV);
        qx = max(-32768, min(32767, qx));
        qy = max(-32768, min(32767, qy));
        s_qpos[i] = ((uint32_t)qx & 0xFFFFu) | ((uint32_t)qy << 16);
    }
    for (int i = threadIdx.x; i < NG16; i += CTA_THREADS)
        s_coarse[i] = g_coarse16[i];
    if (threadIdx.x < NUM_GRAPHS) hist[threadIdx.x] = 0.0f;
    __syncthreads();

    const int P4 = P >> 2;
    const int4* __restrict__ s1v = (const int4*)(epi);
    const int4* __restrict__ s2v = (const int4*)(epi + (size_t)P);
    const int4* __restrict__ e1v = (const int4*)(epi + 2 * (size_t)P);
    const int4* __restrict__ e2v = (const int4*)(epi + 3 * (size_t)P);

    const int stride = gridDim.x * blockDim.x;

    for (int v = blockIdx.x * blockDim.x + threadIdx.x; v < P4; v += stride) {
        int4 s1 = __ldg(s1v + v);
        int4 s2 = __ldg(s2v + v);
        int4 e1 = __ldg(e1v + v);
        int4 e2 = __ldg(e2v + v);

        float2 a1 = get_pos(pos, s_qpos, s1.x, F);
        float2 a2 = get_pos(pos, s_qpos, e1.x, F);
        float2 a3 = get_pos(pos, s_qpos, s2.x, F);
        float2 a4 = get_pos(pos, s_qpos, e2.x, F);
        float2 b1 = get_pos(pos, s_qpos, s1.y, F);
        float2 b2 = get_pos(pos, s_qpos, e1.y, F);
        float2 b3 = get_pos(pos, s_qpos, s2.y, F);
        float2 b4 = get_pos(pos, s_qpos, e2.y, F);
        float2 c1 = get_pos(pos, s_qpos, s1.z, F);
        float2 c2 = get_pos(pos, s_qpos, e1.z, F);
        float2 c3 = get_pos(pos, s_qpos, s2.z, F);
        float2 c4 = get_pos(pos, s_qpos, e2.z, F);
        float2 d1 = get_pos(pos, s_qpos, s1.w, F);
        float2 d2 = get_pos(pos, s_qpos, e1.w, F);
        float2 d3 = get_pos(pos, s_qpos, s2.w, F);
        float2 d4 = get_pos(pos, s_qpos, e2.w, F);

        bool xa = xing_test(a1, a2, a3, a4);
        bool xb = xing_test(b1, b2, b3, b4);
        bool xc = xing_test(c1, c2, c3, c4);
        bool xd = xing_test(d1, d2, d3, d4);

        if (xa) {
            unsigned char b = s_coarse[s1.x >> 4];
            if (b == 255) b = g_batch8[s1.x];
            atomicAdd(&hist[b], 1.0f);
        }
        if (xb) {
            unsigned char b = s_coarse[s1.y >> 4];
            if (b == 255) b = g_batch8[s1.y];
            atomicAdd(&hist[b], 1.0f);
        }
        if (xc) {
            unsigned char b = s_coarse[s1.z >> 4];
            if (b == 255) b = g_batch8[s1.z];
            atomicAdd(&hist[b], 1.0f);
        }
        if (xd) {
            unsigned char b = s_coarse[s1.w >> 4];
            if (b == 255) b = g_batch8[s1.w];
            atomicAdd(&hist[b], 1.0f);
        }
    }

    // Scalar tail (P not divisible by 4) — exact global loads, block 0 only.
    if (blockIdx.x == 0) {
        for (int p = (P4 << 2) + threadIdx.x; p < P; p += blockDim.x) {
            int t1 = __ldg(epi + p);
            int t2 = __ldg(epi + (size_t)P + p);
            int t3 = __ldg(epi + 2 * (size_t)P + p);
            int t4 = __ldg(epi + 3 * (size_t)P + p);
            if (xing_test(__ldg(pos + t1), __ldg(pos + t3),
                          __ldg(pos + t2), __ldg(pos + t4)))
                atomicAdd(&hist[g_batch8[t1]], 1.0f);
        }
    }

    __syncthreads();
    for (int i = threadIdx.x; i < NUM_GRAPHS; i += CTA_THREADS) {
        float h = hist[i];
        if (h != 0.0f) atomicAdd(&out[i], h);
    }
}

extern "C" void kernel_launch(void* const* d_in, const int* in_sizes, int n_in,
                              void* d_out, int out_size) {
    // metadata order: node_pos f32[N,2], edge_index i32[2,E] (UNUSED),
    //                 apsp f32[E] (UNUSED), batch_index i32[N],
    //                 edge_pair_index i32[2,2,P]
    const float2* pos = (const float2*)d_in[0];
    const int* batch_index = (const int*)d_in[3];
    const int* epi = (const int*)d_in[4];
    float* out = (float*)d_out;

    int N = in_sizes[0] / 2;
    if (N > MAX_N) N = MAX_N;        // scratch bound (N is 100000 by spec)
    int P = in_sizes[4] / 4;
    int F = (N < F_SMEM) ? N : F_SMEM;
    int NG16 = (N + 15) >> 4;
    if (NG16 > NG16_MAX) NG16 = NG16_MAX;

    int prep_threads = 256;
    int prep_blocks = (N + prep_threads - 1) / prep_threads;
    prep_kernel<<<prep_blocks, prep_threads>>>(batch_index, out, N);
    int pc_blocks = ((N + 15) / 16 + prep_threads - 1) / prep_threads;
    prep_coarse_kernel<<<pc_blocks, prep_threads>>>(N);

    size_t smem_bytes = (size_t)F * 4 + (size_t)((NG16 + 15) & ~15)
                        + NUM_GRAPHS * sizeof(float);
    cudaFuncSetAttribute(crossings_kernel,
                         cudaFuncAttributeMaxDynamicSharedMemorySize,
                         (int)smem_bytes);

    crossings_kernel<<<148, CTA_THREADS, smem_bytes>>>(pos, epi, out, P, N, F, NG16);
}

// round 6
// speedup vs baseline: 8.8341x; 1.9248x over previous
#include <cuda_runtime.h>
#include <cstdint>

#define EPS 1e-5f
#define NUM_GRAPHS 128
#define MAX_N 131072
#define F_CAP 100352            // quantized nodes held in smem (2B each)
#define NG_CAP 8192             // 16-node coarse batch groups
#define CTA_THREADS 1024

#define QR    5.2f
#define QSTEP (2.0f * QR / 254.0f)
#define QINV  (254.0f / (2.0f * QR))
#define QE    (QR / 254.0f)             // max quantization error per coord
#define TE    (2.0f * QE)               // max error of a coord difference
#define CD    (3.0f * TE * TE + 1e-4f)  // constant part of U_d (+fp32 margin)
#define MARGIN 2e-3f                    // product-level fp32 margin

__device__ unsigned char  g_batch8[MAX_N];
__device__ unsigned char  g_coarse16[NG_CAP];
__device__ unsigned short g_qpos16[F_CAP];

// Prologue: zero out, batch->u8, quantize node_pos to 8+8 bits (0xFFFF = out of range).
__global__ void prep_kernel(const int* __restrict__ batch_index,
                            const float2* __restrict__ pos,
                            float* __restrict__ out, int N, int F) {
    int i = blockIdx.x * blockDim.x + threadIdx.x;
    if (i < NUM_GRAPHS) out[i] = 0.0f;
    if (i < N) g_batch8[i] = (unsigned char)batch_index[i];
    if (i < F) {
        float2 p = __ldg(pos + i);
        int qx = __float2int_rn((p.x + QR) * QINV);
        int qy = __float2int_rn((p.y + QR) * QINV);
        bool ok = (qx >= 0) & (qx <= 254) & (qy >= 0) & (qy <= 254)
                  & (p.x == p.x) & (p.y == p.y);
        g_qpos16[i] = ok ? (unsigned short)(qx | (qy << 8)) : (unsigned short)0xFFFF;
    }
}

__global__ void prep_coarse_kernel(int N) {
    int g = blockIdx.x * blockDim.x + threadIdx.x;
    int ng = (N + 15) >> 4;
    if (g >= ng || g >= NG_CAP) return;
    int base = g << 4;
    unsigned char b0 = g_batch8[base];
    unsigned char v = b0;
    int lim = min(16, N - base);
    for (int j = 1; j < lim; j++)
        if (g_batch8[base + j] != b0) { v = 255; break; }
    g_coarse16[g] = v;
}

__device__ __forceinline__ bool xing_exact(float2 p1, float2 p2, float2 p3, float2 p4) {
    float rx = p4.x - p3.x, ry = p4.y - p3.y;
    float d1 = rx * (p1.y - p3.y) - ry * (p1.x - p3.x);
    float d2 = rx * (p2.y - p3.y) - ry * (p2.x - p3.x);
    float qx = p2.x - p1.x, qy = p2.y - p1.y;
    float d3 = qx * (p3.y - p1.y) - qy * (p3.x - p1.x);
    float d4 = qx * (p4.y - p1.y) - qy * (p4.x - p1.x);
    return (d1 * d2 < -EPS) & (d3 * d4 < -EPS);
}

struct SlotIdx { int s1, e1, s2, e2; };

__global__ void __launch_bounds__(CTA_THREADS, 1)
crossings_kernel(const float2* __restrict__ pos,
                 const int* __restrict__ epi,  // [2][2][P]: s1 | s2 | e1 | e2
                 float* __restrict__ out,
                 int P, int F, int NG16) {
    extern __shared__ char smem_raw[];
    unsigned short* s_q = (unsigned short*)smem_raw;                  // F_CAP*2
    unsigned char* s_coarse = (unsigned char*)(smem_raw + F_CAP * 2); // NG_CAP
    float* hist = (float*)(smem_raw + F_CAP * 2 + NG_CAP);

    // Preload quantized table + coarse batch table (coalesced int4 copies).
    {
        int n16 = (F * 2 + 15) >> 4;  // uint4 count covering F entries
        const uint4* src = (const uint4*)g_qpos16;
        uint4* dst = (uint4*)s_q;
        for (int i = threadIdx.x; i < n16; i += CTA_THREADS) dst[i] = src[i];
        int c16 = (NG16 + 15) >> 4;
        const uint4* csrc = (const uint4*)g_coarse16;
        uint4* cdst = (uint4*)s_coarse;
        for (int i = threadIdx.x; i < c16; i += CTA_THREADS) cdst[i] = csrc[i];
    }
    if (threadIdx.x < NUM_GRAPHS) hist[threadIdx.x] = 0.0f;
    __syncthreads();

    const int P2 = P >> 1;
    const int2* __restrict__ s1v = (const int2*)(epi);
    const int2* __restrict__ s2v = (const int2*)(epi + (size_t)P);
    const int2* __restrict__ e1v = (const int2*)(epi + 2 * (size_t)P);
    const int2* __restrict__ e2v = (const int2*)(epi + 3 * (size_t)P);

    const int stride = gridDim.x * blockDim.x;
    const int Fm1 = F - 1;

    for (int v = blockIdx.x * blockDim.x + threadIdx.x; v < P2; v += stride) {
        int2 s1 = __ldg(s1v + v);
        int2 s2 = __ldg(s2v + v);
        int2 e1 = __ldg(e1v + v);
        int2 e2 = __ldg(e2v + v);

        SlotIdx slot[2] = {{s1.x, e1.x, s2.x, e2.x}, {s1.y, e1.y, s2.y, e2.y}};

        #pragma unroll
        for (int sl = 0; sl < 2; sl++) {
            int i1 = slot[sl].s1, i2 = slot[sl].e1, i3 = slot[sl].s2, i4 = slot[sl].e2;
            // smem gathers (clamped; out-of-table forces fallback below)
            unsigned short q1 = s_q[min(i1, Fm1)];
            unsigned short q2 = s_q[min(i2, Fm1)];
            unsigned short q3 = s_q[min(i3, Fm1)];
            unsigned short q4 = s_q[min(i4, Fm1)];
            bool sent = (q1 == 0xFFFF) | (q2 == 0xFFFF) | (q3 == 0xFFFF) |
                        (q4 == 0xFFFF) | (max(max(i1, i2), max(i3, i4)) >= F);

            float p1x = (float)(q1 & 0xFF) * QSTEP - QR, p1y = (float)(q1 >> 8) * QSTEP - QR;
            float p2x = (float)(q2 & 0xFF) * QSTEP - QR, p2y = (float)(q2 >> 8) * QSTEP - QR;
            float p3x = (float)(q3 & 0xFF) * QSTEP - QR, p3y = (float)(q3 >> 8) * QSTEP - QR;
            float p4x = (float)(q4 & 0xFF) * QSTEP - QR, p4y = (float)(q4 >> 8) * QSTEP - QR;

            // Quantized orientation test with rigorous error bounds.
            float rx = p4x - p3x, ry = p4y - p3y;
            float ax = p1x - p3x, ay = p1y - p3y;
            float bx = p2x - p3x, by = p2y - p3y;
            float d1 = rx * ay - ry * ax;
            float d2 = rx * by - ry * bx;
            float U1 = TE * (fabsf(rx) + fabsf(ay) + fabsf(ry) + fabsf(ax)) + CD;
            float U2 = TE * (fabsf(rx) + fabsf(by) + fabsf(ry) + fabsf(bx)) + CD;
            float ux = p2x - p1x, uy = p2y - p1y;
            float cx = p3x - p1x, cy = p3y - p1y;
            float ex = p4x - p1x, ey = p4y - p1y;
            float d3 = ux * cy - uy * cx;
            float d4 = ux * ey - uy * ex;
            float U3 = TE * (fabsf(ux) + fabsf(cy) + fabsf(uy) + fabsf(cx)) + CD;
            float U4 = TE * (fabsf(ux) + fabsf(ey) + fabsf(uy) + fabsf(ex)) + CD;

            float P12 = d1 * d2 + EPS;
            float P34 = d3 * d4 + EPS;
            float U12 = fabsf(d1) * U2 + fabsf(d2) * U1 + U1 * U2 + MARGIN;
            float U34 = fabsf(d3) * U4 + fabsf(d4) * U3 + U3 * U4 + MARGIN;

            bool ct = (P12 < -U12) & (P34 < -U34);
            bool cf = (P12 > U12) | (P34 > U34);
            bool cross = ct;
            if (sent | (!ct & !cf)) {
                // Uncertain: exact re-test via L1tex (rare lanes only).
                cross = xing_exact(__ldg(pos + i1), __ldg(pos + i2),
                                   __ldg(pos + i3), __ldg(pos + i4));
            }
            if (cross) {
                unsigned char b = s_coarse[i1 >> 4];
                if (b == 255) b = g_batch8[i1];
                atomicAdd(&hist[b], 1.0f);
            }
        }
    }

    // Scalar tail (P odd) — exact path, block 0 only.
    if (blockIdx.x == 0) {
        for (int p = (P2 << 1) + threadIdx.x; p < P; p += blockDim.x) {
            int t1 = __ldg(epi + p);
            int t2 = __ldg(epi + (size_t)P + p);
            int t3 = __ldg(epi + 2 * (size_t)P + p);
            int t4 = __ldg(epi + 3 * (size_t)P + p);
            if (xing_exact(__ldg(pos + t1), __ldg(pos + t3),
                           __ldg(pos + t2), __ldg(pos + t4)))
                atomicAdd(&hist[g_batch8[t1]], 1.0f);
        }
    }

    __syncthreads();
    for (int i = threadIdx.x; i < NUM_GRAPHS; i += CTA_THREADS) {
        float h = hist[i];
        if (h != 0.0f) atomicAdd(&out[i], h);
    }
}

extern "C" void kernel_launch(void* const* d_in, const int* in_sizes, int n_in,
                              void* d_out, int out_size) {
    // metadata order: node_pos f32[N,2], edge_index i32[2,E] (UNUSED),
    //                 apsp f32[E] (UNUSED), batch_index i32[N],
    //                 edge_pair_index i32[2,2,P]
    const float2* pos = (const float2*)d_in[0];
    const int* batch_index = (const int*)d_in[3];
    const int* epi = (const int*)d_in[4];
    float* out = (float*)d_out;

    int N = in_sizes[0] / 2;
    if (N > MAX_N) N = MAX_N;          // scratch bound (N is 100000 by spec)
    int P = in_sizes[4] / 4;
    int F = (N < F_CAP) ? N : F_CAP;
    int NG16 = (N + 15) >> 4;
    if (NG16 > NG_CAP) NG16 = NG_CAP;

    int prep_threads = 256;
    int prep_blocks = (N + prep_threads - 1) / prep_threads;
    prep_kernel<<<prep_blocks, prep_threads>>>(batch_index, pos, out, N, F);
    int pc_blocks = ((N + 15) / 16 + prep_threads - 1) / prep_threads;
    prep_coarse_kernel<<<pc_blocks, prep_threads>>>(N);

    size_t smem_bytes = (size_t)F_CAP * 2 + NG_CAP + NUM_GRAPHS * sizeof(float);
    cudaFuncSetAttribute(crossings_kernel,
                         cudaFuncAttributeMaxDynamicSharedMemorySize,
                         (int)smem_bytes);

    crossings_kernel<<<148, CTA_THREADS, smem_bytes>>>(pos, epi, out, P, F, NG16);
}